// round 12
// baseline (speedup 1.0000x reference)
#include <cuda_runtime.h>
#include <stdint.h>
#include <math.h>

// ============================================================================
// SPEClassifier on GB300. D=256, K=512, L=64, B=8, S=16, C=64.
// R12: R11 (measured-best) + single change: __launch_bounds__(128, 14) on
// main_kernel to cap regs 39->36 and lift occupancy 72% -> ~87%.
// Issue floor ~342us, alu floor ~326us; chasing issue rate.
// ============================================================================

// ---------------- device scratch (no allocation allowed) -------------------
__device__ int   g_order[512];
__device__ float g_qm[8*64*256];
__device__ float g_qv[8*64*256];
__device__ float g_pm[2*64*256];
__device__ float g_pv[2*64*256];
__device__ float g_pC[2*64];
__device__ float g_lm[2*4*64*64];
__device__ float g_tl[2*4*64*16*64];

// ---------------- host threefry (key derivation) ---------------------------
static inline void tf2x32_host(uint32_t k0, uint32_t k1, uint32_t x0, uint32_t x1,
                               uint32_t* o0, uint32_t* o1) {
  uint32_t k2 = k0 ^ k1 ^ 0x1BD11BDAu;
#define ROTL(x,r) (((x)<<(r))|((x)>>(32-(r))))
#define RND(r) { x0 += x1; x1 = ROTL(x1, r); x1 ^= x0; }
  x0 += k0; x1 += k1;
  RND(13) RND(15) RND(26) RND(6)   x0 += k1; x1 += k2 + 1u;
  RND(17) RND(29) RND(16) RND(24)  x0 += k2; x1 += k0 + 2u;
  RND(13) RND(15) RND(26) RND(6)   x0 += k0; x1 += k1 + 3u;
  RND(17) RND(29) RND(16) RND(24)  x0 += k1; x1 += k2 + 4u;
  RND(13) RND(15) RND(26) RND(6)   x0 += k2; x1 += k0 + 5u;
#undef RND
#undef ROTL
  *o0 = x0; *o1 = x1;
}

// r = a*one + b with runtime-opaque one==1 -> IMAD (fma pipe).
__device__ __forceinline__ uint32_t madd1(uint32_t a, uint32_t b, uint32_t one) {
  uint32_t r;
  asm("mad.lo.u32 %0, %1, %2, %3;" : "=r"(r) : "r"(a), "r"(one), "r"(b));
  return r;
}

// threefry2x32 for counter (0, i), x1i = i + k1 pre-added. Returns x0 ^ x1.
__device__ __forceinline__ uint32_t tf_bits(uint32_t x1i, uint32_t k0, uint32_t k1,
                                            uint32_t k2, uint32_t one) {
  uint32_t x0 = madd1(k0, x1i, one);
  uint32_t x1 = __funnelshift_l(x1i, x1i, 13) ^ x0;
#define RND(r) { x0 = madd1(x0, x1, one); x1 = __funnelshift_l(x1, x1, r) ^ x0; }
  RND(15) RND(26) RND(6)
  x0 = madd1(x0, k1, one); x1 = madd1(x1, k2 + 1u, one);
  RND(17) RND(29) RND(16) RND(24)
  x0 = madd1(x0, k2, one); x1 = madd1(x1, k0 + 2u, one);
  RND(13) RND(15) RND(26) RND(6)
  x0 = madd1(x0, k0, one); x1 = madd1(x1, k1 + 3u, one);
  RND(17) RND(29) RND(16) RND(24)
  x0 = madd1(x0, k1, one); x1 = madd1(x1, k2 + 4u, one);
  RND(13) RND(15) RND(26) RND(6)
  x0 = madd1(x0, k2, one); x1 = madd1(x1, k0 + 5u, one);
#undef RND
  return x0 ^ x1;
}

// ---------------- f32x2 packed helpers --------------------------------------
__device__ __forceinline__ uint64_t fma2_(uint64_t a, uint64_t b, uint64_t c) {
  uint64_t d;
  asm("fma.rn.f32x2 %0, %1, %2, %3;" : "=l"(d) : "l"(a), "l"(b), "l"(c));
  return d;
}
__device__ __forceinline__ uint64_t mul2_(uint64_t a, uint64_t b) {
  uint64_t d;
  asm("mul.rn.f32x2 %0, %1, %2;" : "=l"(d) : "l"(a), "l"(b));
  return d;
}
__device__ __forceinline__ uint64_t add2_(uint64_t a, uint64_t b) {
  uint64_t d;
  asm("add.rn.f32x2 %0, %1, %2;" : "=l"(d) : "l"(a), "l"(b));
  return d;
}
__device__ __forceinline__ uint64_t pkuu(uint32_t lo, uint32_t hi) {
  uint64_t d;
  asm("mov.b64 %0, {%1, %2};" : "=l"(d) : "r"(lo), "r"(hi));
  return d;
}
__device__ __forceinline__ uint64_t pkff(float lo, float hi) {
  uint64_t d;
  asm("mov.b64 %0, {%1, %2};" : "=l"(d) : "f"(lo), "f"(hi));
  return d;
}
__device__ __forceinline__ void upff(uint64_t v, float& lo, float& hi) {
  asm("mov.b64 {%0, %1}, %2;" : "=f"(lo), "=f"(hi) : "l"(v));
}
__device__ __forceinline__ uint64_t sp2(float x) {
  uint32_t u = __float_as_uint(x);
  return ((uint64_t)u << 32) | (uint64_t)u;
}

// Rare tail: sqrt2*erfinv for w >= 5 (scalar, immediate coefficients).
__device__ __forceinline__ float tail_e(float w, float u) {
  const float S = 1.41421356237f;
  float sw;
  asm("sqrt.approx.f32 %0, %1;" : "=f"(sw) : "f"(w));
  float v = sw - 3.0f;
  float p = -0.000200214257f * S;
  p = fmaf(p, v, 0.000100950558f * S);
  p = fmaf(p, v, 0.00134934322f * S);
  p = fmaf(p, v, -0.00367342844f * S);
  p = fmaf(p, v, 0.00573950773f * S);
  p = fmaf(p, v, -0.0076224613f * S);
  p = fmaf(p, v, 0.00943887047f * S);
  p = fmaf(p, v, 1.00167406f * S);
  p = fmaf(p, v, 2.83297682f * S);
  return p * u;
}

// Two N(0,1) samples from two random words; returns PACKED (e0,e1). R8 exact.
__device__ __forceinline__ uint64_t pair_normals(uint32_t bits0, uint32_t bits1) {
  const float S = 1.41421356237f;
  uint32_t m0, m1;
  asm("mad.hi.u32 %0, %1, %2, %3;" : "=r"(m0)
      : "r"(bits0), "n"(0x800000), "n"(0x3f800000));
  asm("mad.hi.u32 %0, %1, %2, %3;" : "=r"(m1)
      : "r"(bits1), "n"(0x800000), "n"(0x3f800000));
  uint64_t M = pkuu(m0, m1);
  uint64_t F = add2_(M, sp2(-1.0f));                    // f in [0,1), exact
  uint64_t U = fma2_(F, sp2(2.0f), sp2(-0.99999994f));  // uniform [LO,1)
  uint64_t Zm = fma2_(U, U, sp2(-1.0f));                // u^2-1 = -(1-u^2)
  float zm0, zm1; upff(Zm, zm0, zm1);
  float l0 = __log2f(fabsf(zm0));                       // MUFU.LG2(|zm|)
  float l1 = __log2f(fabsf(zm1));
  uint64_t V = fma2_(pkff(l0, l1), sp2(-0.69314718056f), sp2(-2.5f)); // w-2.5
  uint64_t P = sp2(2.81022636e-08f * S);
  P = fma2_(P, V, sp2(3.43273939e-07f * S));
  P = fma2_(P, V, sp2(-3.5233877e-06f * S));
  P = fma2_(P, V, sp2(-4.39150654e-06f * S));
  P = fma2_(P, V, sp2(0.00021858087f * S));
  P = fma2_(P, V, sp2(-0.00125372503f * S));
  P = fma2_(P, V, sp2(-0.00417768164f * S));
  P = fma2_(P, V, sp2(0.246640727f * S));
  P = fma2_(P, V, sp2(1.50140941f * S));
  uint64_t E = mul2_(P, U);
  // tail: w >= 5 <=> zm >= -e^-5 (~0.34%/sample)
  bool t0 = zm0 > -6.7379470e-3f;
  bool t1 = zm1 > -6.7379470e-3f;
  if (__any_sync(0xffffffffu, t0 || t1)) {
    float e0, e1, u0, u1, v0, v1;
    upff(E, e0, e1);
    upff(U, u0, u1);
    upff(V, v0, v1);
    if (t0) e0 = tail_e(v0 + 2.5f, u0);
    if (t1) e1 = tail_e(v1 + 2.5f, u1);
    E = pkff(e0, e1);
  }
  return E;
}

// ---------------- K1: stable counting "argsort" of labels ------------------
__global__ void order_kernel(const int* __restrict__ labels32) {
  __shared__ int slab[512];
  __shared__ int is64;
  int t = threadIdx.x;
  slab[t] = labels32[t];
  if (t == 0) is64 = 1;
  __syncthreads();
  if ((t & 1) && slab[t] != 0) atomicAnd(&is64, 0);
  __syncthreads();
  int c = is64 ? labels32[2 * t] : slab[t];
  __syncthreads();
  slab[t] = c;
  __syncthreads();
  int occ = 0;
  for (int i = 0; i < t; i++) occ += (slab[i] == c) ? 1 : 0;
  if (c >= 0 && c < 64 && occ < 8)
    g_order[occ * 64 + c] = t;
}

// ---------------- K2: gather params into class-grouped layout --------------
__global__ void gather_kernel(const float* __restrict__ params) {
  int bx = blockIdx.x;
  int b = bx >> 6, l = bx & 63;
  int d = threadIdx.x;
  int row = g_order[b * 64 + l];
  int o = (b * 64 + l) * 256 + d;
  g_qm[o] = params[row * 512 + d];
  g_qv[o] = expf(params[row * 512 + 256 + d]);
}

// ---------------- K3: fuse support into prototypes per half ----------------
__global__ void proto_kernel(const float* __restrict__ heps) {
  int bx = blockIdx.x;
  int half = bx >> 6, l = bx & 63;
  int d = threadIdx.x;
  float eps_var = expf(*heps);
  int sb = half ? 0 : 4;
  float sinv = 0.f, smi = 0.f;
#pragma unroll
  for (int bi = 0; bi < 4; bi++) {
    int o = ((sb + bi) * 64 + l) * 256 + d;
    float v = eps_var + g_qv[o];
    float inv = 1.0f / v;
    sinv += inv;
    smi = fmaf(g_qm[o], inv, smi);
  }
  float nv = 1.0f / sinv;
  float nm = nv * smi;
  float vp = eps_var + nv;
  float hp = logf(vp);
  int po = (half * 64 + l) * 256 + d;
  g_pm[po] = nm;
  g_pv[po] = vp;
  __shared__ float red[256];
  red[d] = 1.83787707f + hp;
  __syncthreads();
  for (int o = 128; o > 0; o >>= 1) {
    if (d < o) red[d] += red[d + o];
    __syncthreads();
  }
  if (d == 0) g_pC[half * 64 + l] = -0.5f * red[0];
}

// ---------------- K4: main Monte-Carlo kernel (R8 + occupancy cap) ----------
__global__ __launch_bounds__(128, 14) void main_kernel(uint32_t s1k0, uint32_t s1k1,
                                                       uint32_t s2k0, uint32_t s2k1,
                                                       uint32_t one) {
  int bx = blockIdx.x;
  int j = bx & 63, l = (bx >> 6) & 63, b = (bx >> 12) & 3, half = bx >> 14;
  uint32_t k0 = half ? s2k0 : s1k0;
  uint32_t k1 = half ? s2k1 : s1k1;
  uint32_t k2 = k0 ^ k1 ^ 0x1BD11BDAu;
  int qb = half * 4 + b;

  __shared__ unsigned long long a2_s[256];   // splat (a, a)
  __shared__ unsigned long long b2_s[256];   // splat (beta, beta)
  __shared__ float red4[4];

  int tid = threadIdx.x;
  int lane = tid & 31, warp = tid >> 5;

  const float* qm = g_qm + (qb * 64 + l) * 256;
  const float* qv = g_qv + (qb * 64 + l) * 256;
  const float* pm = g_pm + (half * 64 + j) * 256;
  const float* pv = g_pv + (half * 64 + j) * 256;

  float lmsum = 0.f;
#pragma unroll
  for (int dd = 0; dd < 2; dd++) {
    int d = tid + dd * 128;
    float m1 = qm[d], v1 = qv[d], m2 = pm[d], v2 = pv[d];
    float vs = v1 + v2;
    float rvs = 1.0f / vs;
    float dm = m1 - m2;
    float a = dm * sqrtf(v2) * rvs;
    float bb = sqrtf(v1 * rvs);
    a2_s[d] = pkff(a, a);
    b2_s[d] = pkff(bb, bb);
    lmsum += 1.8378770664f + logf(vs) + dm * dm * rvs;
  }
  for (int o = 16; o > 0; o >>= 1) lmsum += __shfl_xor_sync(0xffffffffu, lmsum, o);
  if (lane == 0) red4[warp] = lmsum;
  __syncthreads();
  if (tid == 0) {
    float s = red4[0] + red4[1] + red4[2] + red4[3];
    g_lm[((half * 4 + b) * 64 + l) * 64 + j] = -0.5f * s;
  }

  float Cj = g_pC[half * 64 + j];

  uint32_t i00 = ((((uint32_t)(b * 64 + l)) * 16u + (uint32_t)warp) * 64u +
                  (uint32_t)j) * 256u + (uint32_t)lane;
  uint32_t k1p0 = k1 + i00;
  uint32_t k1p1 = k1p0 + 65536u;
  uint32_t k1p2 = k1p0 + 131072u;
  uint32_t k1p3 = k1p0 + 196608u;

  uint64_t ACC01 = 0, ACC23 = 0;       // packed (acc_s, acc_{s+4}) pairs

#pragma unroll 2
  for (int u = 0; u < 8; u++) {
    uint64_t A2 = a2_s[lane + 32 * u];
    uint64_t B2 = b2_s[lane + 32 * u];
    uint32_t du = 32u * (uint32_t)u;

    // pair A: s = warp, warp+4
    {
      uint32_t c0 = tf_bits(madd1(du, k1p0, one), k0, k1, k2, one);
      uint32_t c1 = tf_bits(madd1(du, k1p1, one), k0, k1, k2, one);
      uint64_t E = pair_normals(c0, c1);
      uint64_t T = fma2_(B2, E, A2);
      ACC01 = fma2_(T, T, ACC01);
    }
    // pair B: s = warp+8, warp+12
    {
      uint32_t c2 = tf_bits(madd1(du, k1p2, one), k0, k1, k2, one);
      uint32_t c3 = tf_bits(madd1(du, k1p3, one), k0, k1, k2, one);
      uint64_t E = pair_normals(c2, c3);
      uint64_t T = fma2_(B2, E, A2);
      ACC23 = fma2_(T, T, ACC23);
    }
  }

  float acc0, acc1, acc2, acc3;
  upff(ACC01, acc0, acc1);
  upff(ACC23, acc2, acc3);

#pragma unroll
  for (int o = 16; o > 0; o >>= 1) {
    acc0 += __shfl_xor_sync(0xffffffffu, acc0, o);
    acc1 += __shfl_xor_sync(0xffffffffu, acc1, o);
    acc2 += __shfl_xor_sync(0xffffffffu, acc2, o);
    acc3 += __shfl_xor_sync(0xffffffffu, acc3, o);
  }
  if (lane == 0) {
    int base = (((half * 4 + b) * 64 + l) * 16 + warp) * 64 + j;
    g_tl[base]           = Cj - 0.5f * acc0;
    g_tl[base + 4 * 64]  = Cj - 0.5f * acc1;
    g_tl[base + 8 * 64]  = Cj - 0.5f * acc2;
    g_tl[base + 12 * 64] = Cj - 0.5f * acc3;
  }
}

// ---------------- K5: logsumexps + scatter (warp per s) ---------------------
__global__ __launch_bounds__(512) void finalize_kernel(float* __restrict__ out) {
  int bx = blockIdx.x;
  int l = bx & 63, b = (bx >> 6) & 3, half = bx >> 8;
  int tid = threadIdx.x;
  int lane = tid & 31, warp = tid >> 5;   // warp = s (0..15)

  __shared__ float nls[16];
  __shared__ float Msh;

  int base = (((half * 4 + b) * 64 + l) * 16 + warp) * 64;
  float v0 = g_tl[base + lane];
  float v1 = g_tl[base + 32 + lane];
  float mx = fmaxf(v0, v1);
#pragma unroll
  for (int o = 16; o > 0; o >>= 1) mx = fmaxf(mx, __shfl_xor_sync(0xffffffffu, mx, o));
  float sm = expf(v0 - mx) + expf(v1 - mx);
#pragma unroll
  for (int o = 16; o > 0; o >>= 1) sm += __shfl_xor_sync(0xffffffffu, sm, o);
  if (lane == 0) nls[warp] = -(mx + logf(sm));   // -lse over j for this s
  __syncthreads();

  if (warp == 0) {
    float v = (lane < 16) ? nls[lane] : -3.4e38f;
    float m2 = v;
#pragma unroll
    for (int o = 16; o > 0; o >>= 1) m2 = fmaxf(m2, __shfl_xor_sync(0xffffffffu, m2, o));
    float s2 = (lane < 16) ? expf(v - m2) : 0.f;
#pragma unroll
    for (int o = 16; o > 0; o >>= 1) s2 += __shfl_xor_sync(0xffffffffu, s2, o);
    if (lane == 0) Msh = m2 + logf(s2) - 2.7725887f;  // lse_s(-lse_j) - log 16
  }
  __syncthreads();

  if (tid < 64) {
    int row = g_order[(half * 4 + b) * 64 + l];
    out[row * 64 + tid] = g_lm[((half * 4 + b) * 64 + l) * 64 + tid] + Msh;
  }
}

// ---------------- launcher ---------------------------------------------------
extern "C" void kernel_launch(void* const* d_in, const int* in_sizes, int n_in,
                              void* d_out, int out_size) {
  const float* params = nullptr;
  const float* heps   = nullptr;
  const int*   labels = nullptr;
  for (int i = 0; i < n_in; i++) {
    if (in_sizes[i] == 1) heps = (const float*)d_in[i];
    else if (in_sizes[i] == 512) labels = (const int*)d_in[i];
    else params = (const float*)d_in[i];
  }
  if (!params) params = (const float*)d_in[0];
  if (!heps)   heps   = (const float*)d_in[1];
  if (!labels) labels = (const int*)d_in[2];

  float* out = (float*)d_out;
  (void)out_size;

  uint32_t s1k0, s1k1, s2k0, s2k1;
  tf2x32_host(0u, 42u, 0u, 0u, &s1k0, &s1k1);
  tf2x32_host(0u, 42u, 0u, 1u, &s2k0, &s2k1);

  order_kernel<<<1, 512>>>(labels);
  gather_kernel<<<512, 256>>>(params);
  proto_kernel<<<128, 256>>>(heps);
  main_kernel<<<32768, 128>>>(s1k0, s1k1, s2k0, s2k1, 1u);
  finalize_kernel<<<512, 512>>>(out);
}

// round 13
// speedup vs baseline: 1.0302x; 1.0302x over previous
#include <cuda_runtime.h>
#include <stdint.h>
#include <math.h>

// ============================================================================
// SPEClassifier on GB300. D=256, K=512, L=64, B=8, S=16, C=64.
// R13: R11 (measured-best, main=388.6us) + ONE change: cheaper tail handling
// in pair_normals — single FSETP envelope via fmax, and a PACKED f32x2 tail
// poly in the rare block (bit-identical per-lane results, ~half the rare
// cost). Everything else byte-identical to R11.
// ============================================================================

// ---------------- device scratch (no allocation allowed) -------------------
__device__ int   g_order[512];
__device__ float g_qm[8*64*256];
__device__ float g_qv[8*64*256];
__device__ float g_pm[2*64*256];
__device__ float g_pv[2*64*256];
__device__ float g_pC[2*64];
__device__ float g_lm[2*4*64*64];
__device__ float g_tl[2*4*64*16*64];

// ---------------- host threefry (key derivation) ---------------------------
static inline void tf2x32_host(uint32_t k0, uint32_t k1, uint32_t x0, uint32_t x1,
                               uint32_t* o0, uint32_t* o1) {
  uint32_t k2 = k0 ^ k1 ^ 0x1BD11BDAu;
#define ROTL(x,r) (((x)<<(r))|((x)>>(32-(r))))
#define RND(r) { x0 += x1; x1 = ROTL(x1, r); x1 ^= x0; }
  x0 += k0; x1 += k1;
  RND(13) RND(15) RND(26) RND(6)   x0 += k1; x1 += k2 + 1u;
  RND(17) RND(29) RND(16) RND(24)  x0 += k2; x1 += k0 + 2u;
  RND(13) RND(15) RND(26) RND(6)   x0 += k0; x1 += k1 + 3u;
  RND(17) RND(29) RND(16) RND(24)  x0 += k1; x1 += k2 + 4u;
  RND(13) RND(15) RND(26) RND(6)   x0 += k2; x1 += k0 + 5u;
#undef RND
#undef ROTL
  *o0 = x0; *o1 = x1;
}

// r = a*one + b with runtime-opaque one==1 -> IMAD (fma pipe).
__device__ __forceinline__ uint32_t madd1(uint32_t a, uint32_t b, uint32_t one) {
  uint32_t r;
  asm("mad.lo.u32 %0, %1, %2, %3;" : "=r"(r) : "r"(a), "r"(one), "r"(b));
  return r;
}

// threefry2x32 for counter (0, i), x1i = i + k1 pre-added. Returns x0 ^ x1.
__device__ __forceinline__ uint32_t tf_bits(uint32_t x1i, uint32_t k0, uint32_t k1,
                                            uint32_t k2, uint32_t one) {
  uint32_t x0 = madd1(k0, x1i, one);
  uint32_t x1 = __funnelshift_l(x1i, x1i, 13) ^ x0;
#define RND(r) { x0 = madd1(x0, x1, one); x1 = __funnelshift_l(x1, x1, r) ^ x0; }
  RND(15) RND(26) RND(6)
  x0 = madd1(x0, k1, one); x1 = madd1(x1, k2 + 1u, one);
  RND(17) RND(29) RND(16) RND(24)
  x0 = madd1(x0, k2, one); x1 = madd1(x1, k0 + 2u, one);
  RND(13) RND(15) RND(26) RND(6)
  x0 = madd1(x0, k0, one); x1 = madd1(x1, k1 + 3u, one);
  RND(17) RND(29) RND(16) RND(24)
  x0 = madd1(x0, k1, one); x1 = madd1(x1, k2 + 4u, one);
  RND(13) RND(15) RND(26) RND(6)
  x0 = madd1(x0, k2, one); x1 = madd1(x1, k0 + 5u, one);
#undef RND
  return x0 ^ x1;
}

// ---------------- f32x2 packed helpers --------------------------------------
__device__ __forceinline__ uint64_t fma2_(uint64_t a, uint64_t b, uint64_t c) {
  uint64_t d;
  asm("fma.rn.f32x2 %0, %1, %2, %3;" : "=l"(d) : "l"(a), "l"(b), "l"(c));
  return d;
}
__device__ __forceinline__ uint64_t mul2_(uint64_t a, uint64_t b) {
  uint64_t d;
  asm("mul.rn.f32x2 %0, %1, %2;" : "=l"(d) : "l"(a), "l"(b));
  return d;
}
__device__ __forceinline__ uint64_t add2_(uint64_t a, uint64_t b) {
  uint64_t d;
  asm("add.rn.f32x2 %0, %1, %2;" : "=l"(d) : "l"(a), "l"(b));
  return d;
}
__device__ __forceinline__ uint64_t pkuu(uint32_t lo, uint32_t hi) {
  uint64_t d;
  asm("mov.b64 %0, {%1, %2};" : "=l"(d) : "r"(lo), "r"(hi));
  return d;
}
__device__ __forceinline__ uint64_t pkff(float lo, float hi) {
  uint64_t d;
  asm("mov.b64 %0, {%1, %2};" : "=l"(d) : "f"(lo), "f"(hi));
  return d;
}
__device__ __forceinline__ void upff(uint64_t v, float& lo, float& hi) {
  asm("mov.b64 {%0, %1}, %2;" : "=f"(lo), "=f"(hi) : "l"(v));
}
__device__ __forceinline__ uint64_t sp2(float x) {
  uint32_t u = __float_as_uint(x);
  return ((uint64_t)u << 32) | (uint64_t)u;
}

// Two N(0,1) samples from two random words; returns PACKED (e0,e1).
// Fast path identical to R11. Rare tail (w>=5, ~0.34%/sample): single
// fmax-merged FSETP envelope, packed tail poly (bit-identical per lane).
__device__ __forceinline__ uint64_t pair_normals(uint32_t bits0, uint32_t bits1) {
  const float S = 1.41421356237f;
  const float THR = -6.7379470e-3f;   // zm > THR  <=>  w >= 5
  uint32_t m0, m1;
  asm("mad.hi.u32 %0, %1, %2, %3;" : "=r"(m0)
      : "r"(bits0), "n"(0x800000), "n"(0x3f800000));
  asm("mad.hi.u32 %0, %1, %2, %3;" : "=r"(m1)
      : "r"(bits1), "n"(0x800000), "n"(0x3f800000));
  uint64_t M = pkuu(m0, m1);
  uint64_t F = add2_(M, sp2(-1.0f));                    // f in [0,1), exact
  uint64_t U = fma2_(F, sp2(2.0f), sp2(-0.99999994f));  // uniform [LO,1)
  uint64_t Zm = fma2_(U, U, sp2(-1.0f));                // u^2-1 = -(1-u^2)
  float zm0, zm1; upff(Zm, zm0, zm1);
  float l0 = __log2f(fabsf(zm0));                       // MUFU.LG2(|zm|)
  float l1 = __log2f(fabsf(zm1));
  uint64_t V = fma2_(pkff(l0, l1), sp2(-0.69314718056f), sp2(-2.5f)); // w-2.5
  uint64_t P = sp2(2.81022636e-08f * S);
  P = fma2_(P, V, sp2(3.43273939e-07f * S));
  P = fma2_(P, V, sp2(-3.5233877e-06f * S));
  P = fma2_(P, V, sp2(-4.39150654e-06f * S));
  P = fma2_(P, V, sp2(0.00021858087f * S));
  P = fma2_(P, V, sp2(-0.00125372503f * S));
  P = fma2_(P, V, sp2(-0.00417768164f * S));
  P = fma2_(P, V, sp2(0.246640727f * S));
  P = fma2_(P, V, sp2(1.50140941f * S));
  uint64_t E = mul2_(P, U);
  // envelope: single compare on max(zm0, zm1)
  if (__any_sync(0xffffffffu, fmaxf(zm0, zm1) > THR)) {
    // packed tail: w = v + 2.5; sw = sqrt.approx(w); vt = sw - 3; Giles tail
    uint64_t W2 = add2_(V, sp2(2.5f));
    float w0, w1; upff(W2, w0, w1);
    float s0, s1;
    asm("sqrt.approx.f32 %0, %1;" : "=f"(s0) : "f"(w0));
    asm("sqrt.approx.f32 %0, %1;" : "=f"(s1) : "f"(w1));
    uint64_t VT = add2_(pkff(s0, s1), sp2(-3.0f));
    uint64_t PT = sp2(-0.000200214257f * S);
    PT = fma2_(PT, VT, sp2(0.000100950558f * S));
    PT = fma2_(PT, VT, sp2(0.00134934322f * S));
    PT = fma2_(PT, VT, sp2(-0.00367342844f * S));
    PT = fma2_(PT, VT, sp2(0.00573950773f * S));
    PT = fma2_(PT, VT, sp2(-0.0076224613f * S));
    PT = fma2_(PT, VT, sp2(0.00943887047f * S));
    PT = fma2_(PT, VT, sp2(1.00167406f * S));
    PT = fma2_(PT, VT, sp2(2.83297682f * S));
    uint64_t ET = mul2_(PT, U);
    float e0, e1, et0, et1;
    upff(E, e0, e1);
    upff(ET, et0, et1);
    if (zm0 > THR) e0 = et0;
    if (zm1 > THR) e1 = et1;
    E = pkff(e0, e1);
  }
  return E;
}

// ---------------- K1: stable counting "argsort" of labels ------------------
__global__ void order_kernel(const int* __restrict__ labels32) {
  __shared__ int slab[512];
  __shared__ int is64;
  int t = threadIdx.x;
  slab[t] = labels32[t];
  if (t == 0) is64 = 1;
  __syncthreads();
  if ((t & 1) && slab[t] != 0) atomicAnd(&is64, 0);
  __syncthreads();
  int c = is64 ? labels32[2 * t] : slab[t];
  __syncthreads();
  slab[t] = c;
  __syncthreads();
  int occ = 0;
  for (int i = 0; i < t; i++) occ += (slab[i] == c) ? 1 : 0;
  if (c >= 0 && c < 64 && occ < 8)
    g_order[occ * 64 + c] = t;
}

// ---------------- K2: gather params into class-grouped layout --------------
__global__ void gather_kernel(const float* __restrict__ params) {
  int bx = blockIdx.x;
  int b = bx >> 6, l = bx & 63;
  int d = threadIdx.x;
  int row = g_order[b * 64 + l];
  int o = (b * 64 + l) * 256 + d;
  g_qm[o] = params[row * 512 + d];
  g_qv[o] = expf(params[row * 512 + 256 + d]);
}

// ---------------- K3: fuse support into prototypes per half ----------------
__global__ void proto_kernel(const float* __restrict__ heps) {
  int bx = blockIdx.x;
  int half = bx >> 6, l = bx & 63;
  int d = threadIdx.x;
  float eps_var = expf(*heps);
  int sb = half ? 0 : 4;
  float sinv = 0.f, smi = 0.f;
#pragma unroll
  for (int bi = 0; bi < 4; bi++) {
    int o = ((sb + bi) * 64 + l) * 256 + d;
    float v = eps_var + g_qv[o];
    float inv = 1.0f / v;
    sinv += inv;
    smi = fmaf(g_qm[o], inv, smi);
  }
  float nv = 1.0f / sinv;
  float nm = nv * smi;
  float vp = eps_var + nv;
  float hp = logf(vp);
  int po = (half * 64 + l) * 256 + d;
  g_pm[po] = nm;
  g_pv[po] = vp;
  __shared__ float red[256];
  red[d] = 1.83787707f + hp;
  __syncthreads();
  for (int o = 128; o > 0; o >>= 1) {
    if (d < o) red[d] += red[d + o];
    __syncthreads();
  }
  if (d == 0) g_pC[half * 64 + l] = -0.5f * red[0];
}

// ---------------- K4: main Monte-Carlo kernel (R11 + tail change) -----------
__global__ __launch_bounds__(128) void main_kernel(uint32_t s1k0, uint32_t s1k1,
                                                   uint32_t s2k0, uint32_t s2k1,
                                                   uint32_t one) {
  int bx = blockIdx.x;
  int j = bx & 63, l = (bx >> 6) & 63, b = (bx >> 12) & 3, half = bx >> 14;
  uint32_t k0 = half ? s2k0 : s1k0;
  uint32_t k1 = half ? s2k1 : s1k1;
  uint32_t k2 = k0 ^ k1 ^ 0x1BD11BDAu;
  int qb = half * 4 + b;

  __shared__ unsigned long long a2_s[256];   // splat (a, a)
  __shared__ unsigned long long b2_s[256];   // splat (beta, beta)
  __shared__ float red4[4];

  int tid = threadIdx.x;
  int lane = tid & 31, warp = tid >> 5;

  const float* qm = g_qm + (qb * 64 + l) * 256;
  const float* qv = g_qv + (qb * 64 + l) * 256;
  const float* pm = g_pm + (half * 64 + j) * 256;
  const float* pv = g_pv + (half * 64 + j) * 256;

  float lmsum = 0.f;
#pragma unroll
  for (int dd = 0; dd < 2; dd++) {
    int d = tid + dd * 128;
    float m1 = qm[d], v1 = qv[d], m2 = pm[d], v2 = pv[d];
    float vs = v1 + v2;
    float rvs = 1.0f / vs;
    float dm = m1 - m2;
    float a = dm * sqrtf(v2) * rvs;
    float bb = sqrtf(v1 * rvs);
    a2_s[d] = pkff(a, a);
    b2_s[d] = pkff(bb, bb);
    lmsum += 1.8378770664f + logf(vs) + dm * dm * rvs;
  }
  for (int o = 16; o > 0; o >>= 1) lmsum += __shfl_xor_sync(0xffffffffu, lmsum, o);
  if (lane == 0) red4[warp] = lmsum;
  __syncthreads();
  if (tid == 0) {
    float s = red4[0] + red4[1] + red4[2] + red4[3];
    g_lm[((half * 4 + b) * 64 + l) * 64 + j] = -0.5f * s;
  }

  float Cj = g_pC[half * 64 + j];

  uint32_t i00 = ((((uint32_t)(b * 64 + l)) * 16u + (uint32_t)warp) * 64u +
                  (uint32_t)j) * 256u + (uint32_t)lane;
  uint32_t k1p0 = k1 + i00;
  uint32_t k1p1 = k1p0 + 65536u;
  uint32_t k1p2 = k1p0 + 131072u;
  uint32_t k1p3 = k1p0 + 196608u;

  uint64_t ACC01 = 0, ACC23 = 0;       // packed (acc_s, acc_{s+4}) pairs

#pragma unroll 2
  for (int u = 0; u < 8; u++) {
    uint64_t A2 = a2_s[lane + 32 * u];
    uint64_t B2 = b2_s[lane + 32 * u];
    uint32_t du = 32u * (uint32_t)u;

    // pair A: s = warp, warp+4
    {
      uint32_t c0 = tf_bits(madd1(du, k1p0, one), k0, k1, k2, one);
      uint32_t c1 = tf_bits(madd1(du, k1p1, one), k0, k1, k2, one);
      uint64_t E = pair_normals(c0, c1);
      uint64_t T = fma2_(B2, E, A2);
      ACC01 = fma2_(T, T, ACC01);
    }
    // pair B: s = warp+8, warp+12
    {
      uint32_t c2 = tf_bits(madd1(du, k1p2, one), k0, k1, k2, one);
      uint32_t c3 = tf_bits(madd1(du, k1p3, one), k0, k1, k2, one);
      uint64_t E = pair_normals(c2, c3);
      uint64_t T = fma2_(B2, E, A2);
      ACC23 = fma2_(T, T, ACC23);
    }
  }

  float acc0, acc1, acc2, acc3;
  upff(ACC01, acc0, acc1);
  upff(ACC23, acc2, acc3);

#pragma unroll
  for (int o = 16; o > 0; o >>= 1) {
    acc0 += __shfl_xor_sync(0xffffffffu, acc0, o);
    acc1 += __shfl_xor_sync(0xffffffffu, acc1, o);
    acc2 += __shfl_xor_sync(0xffffffffu, acc2, o);
    acc3 += __shfl_xor_sync(0xffffffffu, acc3, o);
  }
  if (lane == 0) {
    int base = (((half * 4 + b) * 64 + l) * 16 + warp) * 64 + j;
    g_tl[base]           = Cj - 0.5f * acc0;
    g_tl[base + 4 * 64]  = Cj - 0.5f * acc1;
    g_tl[base + 8 * 64]  = Cj - 0.5f * acc2;
    g_tl[base + 12 * 64] = Cj - 0.5f * acc3;
  }
}

// ---------------- K5: logsumexps + scatter (warp per s) ---------------------
__global__ __launch_bounds__(512) void finalize_kernel(float* __restrict__ out) {
  int bx = blockIdx.x;
  int l = bx & 63, b = (bx >> 6) & 3, half = bx >> 8;
  int tid = threadIdx.x;
  int lane = tid & 31, warp = tid >> 5;   // warp = s (0..15)

  __shared__ float nls[16];
  __shared__ float Msh;

  int base = (((half * 4 + b) * 64 + l) * 16 + warp) * 64;
  float v0 = g_tl[base + lane];
  float v1 = g_tl[base + 32 + lane];
  float mx = fmaxf(v0, v1);
#pragma unroll
  for (int o = 16; o > 0; o >>= 1) mx = fmaxf(mx, __shfl_xor_sync(0xffffffffu, mx, o));
  float sm = expf(v0 - mx) + expf(v1 - mx);
#pragma unroll
  for (int o = 16; o > 0; o >>= 1) sm += __shfl_xor_sync(0xffffffffu, sm, o);
  if (lane == 0) nls[warp] = -(mx + logf(sm));   // -lse over j for this s
  __syncthreads();

  if (warp == 0) {
    float v = (lane < 16) ? nls[lane] : -3.4e38f;
    float m2 = v;
#pragma unroll
    for (int o = 16; o > 0; o >>= 1) m2 = fmaxf(m2, __shfl_xor_sync(0xffffffffu, m2, o));
    float s2 = (lane < 16) ? expf(v - m2) : 0.f;
#pragma unroll
    for (int o = 16; o > 0; o >>= 1) s2 += __shfl_xor_sync(0xffffffffu, s2, o);
    if (lane == 0) Msh = m2 + logf(s2) - 2.7725887f;  // lse_s(-lse_j) - log 16
  }
  __syncthreads();

  if (tid < 64) {
    int row = g_order[(half * 4 + b) * 64 + l];
    out[row * 64 + tid] = g_lm[((half * 4 + b) * 64 + l) * 64 + tid] + Msh;
  }
}

// ---------------- launcher ---------------------------------------------------
extern "C" void kernel_launch(void* const* d_in, const int* in_sizes, int n_in,
                              void* d_out, int out_size) {
  const float* params = nullptr;
  const float* heps   = nullptr;
  const int*   labels = nullptr;
  for (int i = 0; i < n_in; i++) {
    if (in_sizes[i] == 1) heps = (const float*)d_in[i];
    else if (in_sizes[i] == 512) labels = (const int*)d_in[i];
    else params = (const float*)d_in[i];
  }
  if (!params) params = (const float*)d_in[0];
  if (!heps)   heps   = (const float*)d_in[1];
  if (!labels) labels = (const int*)d_in[2];

  float* out = (float*)d_out;
  (void)out_size;

  uint32_t s1k0, s1k1, s2k0, s2k1;
  tf2x32_host(0u, 42u, 0u, 0u, &s1k0, &s1k1);
  tf2x32_host(0u, 42u, 0u, 1u, &s2k0, &s2k1);

  order_kernel<<<1, 512>>>(labels);
  gather_kernel<<<512, 256>>>(params);
  proto_kernel<<<128, 256>>>(heps);
  main_kernel<<<32768, 128>>>(s1k0, s1k1, s2k0, s2k1, 1u);
  finalize_kernel<<<512, 512>>>(out);
}

// round 14
// speedup vs baseline: 1.0529x; 1.0221x over previous
#include <cuda_runtime.h>
#include <stdint.h>
#include <math.h>

// ============================================================================
// SPEClassifier on GB300. D=256, K=512, L=64, B=8, S=16, C=64.
// R14: main kernel byte-identical to R11 (measured plateau 388.6us); fuse
// order+gather+proto into ONE setup kernel (ballot-based stable rank, shared
// staging, no global round-trip). 5 launches -> 3.
// ============================================================================

// ---------------- device scratch (no allocation allowed) -------------------
__device__ int   g_order[512];
__device__ float g_qm[8*64*256];
__device__ float g_qv[8*64*256];
__device__ float g_pm[2*64*256];
__device__ float g_pv[2*64*256];
__device__ float g_pC[2*64];
__device__ float g_lm[2*4*64*64];
__device__ float g_tl[2*4*64*16*64];

// ---------------- host threefry (key derivation) ---------------------------
static inline void tf2x32_host(uint32_t k0, uint32_t k1, uint32_t x0, uint32_t x1,
                               uint32_t* o0, uint32_t* o1) {
  uint32_t k2 = k0 ^ k1 ^ 0x1BD11BDAu;
#define ROTL(x,r) (((x)<<(r))|((x)>>(32-(r))))
#define RND(r) { x0 += x1; x1 = ROTL(x1, r); x1 ^= x0; }
  x0 += k0; x1 += k1;
  RND(13) RND(15) RND(26) RND(6)   x0 += k1; x1 += k2 + 1u;
  RND(17) RND(29) RND(16) RND(24)  x0 += k2; x1 += k0 + 2u;
  RND(13) RND(15) RND(26) RND(6)   x0 += k0; x1 += k1 + 3u;
  RND(17) RND(29) RND(16) RND(24)  x0 += k1; x1 += k2 + 4u;
  RND(13) RND(15) RND(26) RND(6)   x0 += k2; x1 += k0 + 5u;
#undef RND
#undef ROTL
  *o0 = x0; *o1 = x1;
}

// r = a*one + b with runtime-opaque one==1 -> IMAD (fma pipe).
__device__ __forceinline__ uint32_t madd1(uint32_t a, uint32_t b, uint32_t one) {
  uint32_t r;
  asm("mad.lo.u32 %0, %1, %2, %3;" : "=r"(r) : "r"(a), "r"(one), "r"(b));
  return r;
}

// threefry2x32 for counter (0, i), x1i = i + k1 pre-added. Returns x0 ^ x1.
__device__ __forceinline__ uint32_t tf_bits(uint32_t x1i, uint32_t k0, uint32_t k1,
                                            uint32_t k2, uint32_t one) {
  uint32_t x0 = madd1(k0, x1i, one);
  uint32_t x1 = __funnelshift_l(x1i, x1i, 13) ^ x0;
#define RND(r) { x0 = madd1(x0, x1, one); x1 = __funnelshift_l(x1, x1, r) ^ x0; }
  RND(15) RND(26) RND(6)
  x0 = madd1(x0, k1, one); x1 = madd1(x1, k2 + 1u, one);
  RND(17) RND(29) RND(16) RND(24)
  x0 = madd1(x0, k2, one); x1 = madd1(x1, k0 + 2u, one);
  RND(13) RND(15) RND(26) RND(6)
  x0 = madd1(x0, k0, one); x1 = madd1(x1, k1 + 3u, one);
  RND(17) RND(29) RND(16) RND(24)
  x0 = madd1(x0, k1, one); x1 = madd1(x1, k2 + 4u, one);
  RND(13) RND(15) RND(26) RND(6)
  x0 = madd1(x0, k2, one); x1 = madd1(x1, k0 + 5u, one);
#undef RND
  return x0 ^ x1;
}

// ---------------- f32x2 packed helpers --------------------------------------
__device__ __forceinline__ uint64_t fma2_(uint64_t a, uint64_t b, uint64_t c) {
  uint64_t d;
  asm("fma.rn.f32x2 %0, %1, %2, %3;" : "=l"(d) : "l"(a), "l"(b), "l"(c));
  return d;
}
__device__ __forceinline__ uint64_t mul2_(uint64_t a, uint64_t b) {
  uint64_t d;
  asm("mul.rn.f32x2 %0, %1, %2;" : "=l"(d) : "l"(a), "l"(b));
  return d;
}
__device__ __forceinline__ uint64_t add2_(uint64_t a, uint64_t b) {
  uint64_t d;
  asm("add.rn.f32x2 %0, %1, %2;" : "=l"(d) : "l"(a), "l"(b));
  return d;
}
__device__ __forceinline__ uint64_t pkuu(uint32_t lo, uint32_t hi) {
  uint64_t d;
  asm("mov.b64 %0, {%1, %2};" : "=l"(d) : "r"(lo), "r"(hi));
  return d;
}
__device__ __forceinline__ uint64_t pkff(float lo, float hi) {
  uint64_t d;
  asm("mov.b64 %0, {%1, %2};" : "=l"(d) : "f"(lo), "f"(hi));
  return d;
}
__device__ __forceinline__ void upff(uint64_t v, float& lo, float& hi) {
  asm("mov.b64 {%0, %1}, %2;" : "=f"(lo), "=f"(hi) : "l"(v));
}
__device__ __forceinline__ uint64_t sp2(float x) {
  uint32_t u = __float_as_uint(x);
  return ((uint64_t)u << 32) | (uint64_t)u;
}

// Rare tail: sqrt2*erfinv for w >= 5 (scalar, immediate coefficients).
__device__ __forceinline__ float tail_e(float w, float u) {
  const float S = 1.41421356237f;
  float sw;
  asm("sqrt.approx.f32 %0, %1;" : "=f"(sw) : "f"(w));
  float v = sw - 3.0f;
  float p = -0.000200214257f * S;
  p = fmaf(p, v, 0.000100950558f * S);
  p = fmaf(p, v, 0.00134934322f * S);
  p = fmaf(p, v, -0.00367342844f * S);
  p = fmaf(p, v, 0.00573950773f * S);
  p = fmaf(p, v, -0.0076224613f * S);
  p = fmaf(p, v, 0.00943887047f * S);
  p = fmaf(p, v, 1.00167406f * S);
  p = fmaf(p, v, 2.83297682f * S);
  return p * u;
}

// Two N(0,1) samples from two random words; returns PACKED (e0,e1). R11 exact.
__device__ __forceinline__ uint64_t pair_normals(uint32_t bits0, uint32_t bits1) {
  const float S = 1.41421356237f;
  uint32_t m0, m1;
  asm("mad.hi.u32 %0, %1, %2, %3;" : "=r"(m0)
      : "r"(bits0), "n"(0x800000), "n"(0x3f800000));
  asm("mad.hi.u32 %0, %1, %2, %3;" : "=r"(m1)
      : "r"(bits1), "n"(0x800000), "n"(0x3f800000));
  uint64_t M = pkuu(m0, m1);
  uint64_t F = add2_(M, sp2(-1.0f));                    // f in [0,1), exact
  uint64_t U = fma2_(F, sp2(2.0f), sp2(-0.99999994f));  // uniform [LO,1)
  uint64_t Zm = fma2_(U, U, sp2(-1.0f));                // u^2-1 = -(1-u^2)
  float zm0, zm1; upff(Zm, zm0, zm1);
  float l0 = __log2f(fabsf(zm0));                       // MUFU.LG2(|zm|)
  float l1 = __log2f(fabsf(zm1));
  uint64_t V = fma2_(pkff(l0, l1), sp2(-0.69314718056f), sp2(-2.5f)); // w-2.5
  uint64_t P = sp2(2.81022636e-08f * S);
  P = fma2_(P, V, sp2(3.43273939e-07f * S));
  P = fma2_(P, V, sp2(-3.5233877e-06f * S));
  P = fma2_(P, V, sp2(-4.39150654e-06f * S));
  P = fma2_(P, V, sp2(0.00021858087f * S));
  P = fma2_(P, V, sp2(-0.00125372503f * S));
  P = fma2_(P, V, sp2(-0.00417768164f * S));
  P = fma2_(P, V, sp2(0.246640727f * S));
  P = fma2_(P, V, sp2(1.50140941f * S));
  uint64_t E = mul2_(P, U);
  // tail: w >= 5 <=> zm >= -e^-5 (~0.34%/sample)
  bool t0 = zm0 > -6.7379470e-3f;
  bool t1 = zm1 > -6.7379470e-3f;
  if (__any_sync(0xffffffffu, t0 || t1)) {
    float e0, e1, u0, u1, v0, v1;
    upff(E, e0, e1);
    upff(U, u0, u1);
    upff(V, v0, v1);
    if (t0) e0 = tail_e(v0 + 2.5f, u0);
    if (t1) e1 = tail_e(v1 + 2.5f, u1);
    E = pkff(e0, e1);
  }
  return E;
}

// ---------------- K1: fused setup (order + gather + prototypes) ------------
// One block per class l (64 blocks, 256 threads). Ballot-ranked stable order,
// params staged in shared, both halves' prototypes computed in-block.
__global__ __launch_bounds__(256) void setup_kernel(const float* __restrict__ params,
                                                    const int* __restrict__ labels32,
                                                    const float* __restrict__ heps) {
  int l = blockIdx.x;          // class
  int t = threadIdx.x;         // 0..255
  int lane = t & 31, w = t >> 5;

  __shared__ int labs[512];
  __shared__ unsigned ball[16];
  __shared__ int rows[8];
  __shared__ int odd_nz;
  __shared__ float sm_m[8][256];
  __shared__ float sm_v[8][256];
  __shared__ float red[256];

  if (t == 0) odd_nz = 0;
  __syncthreads();
  // dtype detect: any odd int32 word nonzero -> int32 labels
  if (labels32[2 * t + 1] != 0) atomicOr(&odd_nz, 1);
  __syncthreads();
  int stride = odd_nz ? 1 : 2;   // int64 (little-endian) -> stride 2
  labs[t]       = labels32[t * stride];
  labs[t + 256] = labels32[(t + 256) * stride];
  __syncthreads();

  bool f0 = (labs[t] == l);
  bool f1 = (labs[t + 256] == l);
  unsigned b0 = __ballot_sync(0xffffffffu, f0);
  unsigned b1 = __ballot_sync(0xffffffffu, f1);
  if (lane == 0) { ball[w] = b0; ball[w + 8] = b1; }
  __syncthreads();
  if (f0) {
    int r = __popc(b0 & ((1u << lane) - 1u));
    for (int k = 0; k < w; k++) r += __popc(ball[k]);
    if (r < 8) rows[r] = t;
  }
  if (f1) {
    int r = __popc(b1 & ((1u << lane) - 1u));
    for (int k = 0; k < 8 + w; k++) r += __popc(ball[k]);
    if (r < 8) rows[r] = t + 256;
  }
  __syncthreads();

  // gather 8 rows into shared + global
#pragma unroll
  for (int b = 0; b < 8; b++) {
    int row = rows[b];
    float m = params[row * 512 + t];
    float v = expf(params[row * 512 + 256 + t]);
    sm_m[b][t] = m; sm_v[b][t] = v;
    g_qm[(b * 64 + l) * 256 + t] = m;
    g_qv[(b * 64 + l) * 256 + t] = v;
  }
  if (t < 8) g_order[t * 64 + l] = rows[t];
  __syncthreads();

  float eps_var = expf(*heps);
#pragma unroll
  for (int half = 0; half < 2; half++) {
    int sb = half ? 0 : 4;       // half0 support = b 4..7, half1 = b 0..3
    float sinv = 0.f, smi = 0.f;
#pragma unroll
    for (int bi = 0; bi < 4; bi++) {
      float v = eps_var + sm_v[sb + bi][t];
      float inv = 1.0f / v;
      sinv += inv;
      smi = fmaf(sm_m[sb + bi][t], inv, smi);
    }
    float nv = 1.0f / sinv;
    float nm = nv * smi;
    float vp = eps_var + nv;
    float hp = logf(vp);
    g_pm[(half * 64 + l) * 256 + t] = nm;
    g_pv[(half * 64 + l) * 256 + t] = vp;
    red[t] = 1.83787707f + hp;
    __syncthreads();
    for (int o = 128; o > 0; o >>= 1) {
      if (t < o) red[t] += red[t + o];
      __syncthreads();
    }
    if (t == 0) g_pC[half * 64 + l] = -0.5f * red[0];
    __syncthreads();
  }
}

// ---------------- K2: main Monte-Carlo kernel (byte-identical to R11) -------
__global__ __launch_bounds__(128) void main_kernel(uint32_t s1k0, uint32_t s1k1,
                                                   uint32_t s2k0, uint32_t s2k1,
                                                   uint32_t one) {
  int bx = blockIdx.x;
  int j = bx & 63, l = (bx >> 6) & 63, b = (bx >> 12) & 3, half = bx >> 14;
  uint32_t k0 = half ? s2k0 : s1k0;
  uint32_t k1 = half ? s2k1 : s1k1;
  uint32_t k2 = k0 ^ k1 ^ 0x1BD11BDAu;
  int qb = half * 4 + b;

  __shared__ unsigned long long a2_s[256];   // splat (a, a)
  __shared__ unsigned long long b2_s[256];   // splat (beta, beta)
  __shared__ float red4[4];

  int tid = threadIdx.x;
  int lane = tid & 31, warp = tid >> 5;

  const float* qm = g_qm + (qb * 64 + l) * 256;
  const float* qv = g_qv + (qb * 64 + l) * 256;
  const float* pm = g_pm + (half * 64 + j) * 256;
  const float* pv = g_pv + (half * 64 + j) * 256;

  float lmsum = 0.f;
#pragma unroll
  for (int dd = 0; dd < 2; dd++) {
    int d = tid + dd * 128;
    float m1 = qm[d], v1 = qv[d], m2 = pm[d], v2 = pv[d];
    float vs = v1 + v2;
    float rvs = 1.0f / vs;
    float dm = m1 - m2;
    float a = dm * sqrtf(v2) * rvs;
    float bb = sqrtf(v1 * rvs);
    a2_s[d] = pkff(a, a);
    b2_s[d] = pkff(bb, bb);
    lmsum += 1.8378770664f + logf(vs) + dm * dm * rvs;
  }
  for (int o = 16; o > 0; o >>= 1) lmsum += __shfl_xor_sync(0xffffffffu, lmsum, o);
  if (lane == 0) red4[warp] = lmsum;
  __syncthreads();
  if (tid == 0) {
    float s = red4[0] + red4[1] + red4[2] + red4[3];
    g_lm[((half * 4 + b) * 64 + l) * 64 + j] = -0.5f * s;
  }

  float Cj = g_pC[half * 64 + j];

  uint32_t i00 = ((((uint32_t)(b * 64 + l)) * 16u + (uint32_t)warp) * 64u +
                  (uint32_t)j) * 256u + (uint32_t)lane;
  uint32_t k1p0 = k1 + i00;
  uint32_t k1p1 = k1p0 + 65536u;
  uint32_t k1p2 = k1p0 + 131072u;
  uint32_t k1p3 = k1p0 + 196608u;

  uint64_t ACC01 = 0, ACC23 = 0;       // packed (acc_s, acc_{s+4}) pairs

#pragma unroll 2
  for (int u = 0; u < 8; u++) {
    uint64_t A2 = a2_s[lane + 32 * u];
    uint64_t B2 = b2_s[lane + 32 * u];
    uint32_t du = 32u * (uint32_t)u;

    // pair A: s = warp, warp+4
    {
      uint32_t c0 = tf_bits(madd1(du, k1p0, one), k0, k1, k2, one);
      uint32_t c1 = tf_bits(madd1(du, k1p1, one), k0, k1, k2, one);
      uint64_t E = pair_normals(c0, c1);
      uint64_t T = fma2_(B2, E, A2);
      ACC01 = fma2_(T, T, ACC01);
    }
    // pair B: s = warp+8, warp+12
    {
      uint32_t c2 = tf_bits(madd1(du, k1p2, one), k0, k1, k2, one);
      uint32_t c3 = tf_bits(madd1(du, k1p3, one), k0, k1, k2, one);
      uint64_t E = pair_normals(c2, c3);
      uint64_t T = fma2_(B2, E, A2);
      ACC23 = fma2_(T, T, ACC23);
    }
  }

  float acc0, acc1, acc2, acc3;
  upff(ACC01, acc0, acc1);
  upff(ACC23, acc2, acc3);

#pragma unroll
  for (int o = 16; o > 0; o >>= 1) {
    acc0 += __shfl_xor_sync(0xffffffffu, acc0, o);
    acc1 += __shfl_xor_sync(0xffffffffu, acc1, o);
    acc2 += __shfl_xor_sync(0xffffffffu, acc2, o);
    acc3 += __shfl_xor_sync(0xffffffffu, acc3, o);
  }
  if (lane == 0) {
    int base = (((half * 4 + b) * 64 + l) * 16 + warp) * 64 + j;
    g_tl[base]           = Cj - 0.5f * acc0;
    g_tl[base + 4 * 64]  = Cj - 0.5f * acc1;
    g_tl[base + 8 * 64]  = Cj - 0.5f * acc2;
    g_tl[base + 12 * 64] = Cj - 0.5f * acc3;
  }
}

// ---------------- K3: logsumexps + scatter (warp per s) ---------------------
__global__ __launch_bounds__(512) void finalize_kernel(float* __restrict__ out) {
  int bx = blockIdx.x;
  int l = bx & 63, b = (bx >> 6) & 3, half = bx >> 8;
  int tid = threadIdx.x;
  int lane = tid & 31, warp = tid >> 5;   // warp = s (0..15)

  __shared__ float nls[16];
  __shared__ float Msh;

  int base = (((half * 4 + b) * 64 + l) * 16 + warp) * 64;
  float v0 = g_tl[base + lane];
  float v1 = g_tl[base + 32 + lane];
  float mx = fmaxf(v0, v1);
#pragma unroll
  for (int o = 16; o > 0; o >>= 1) mx = fmaxf(mx, __shfl_xor_sync(0xffffffffu, mx, o));
  float sm = expf(v0 - mx) + expf(v1 - mx);
#pragma unroll
  for (int o = 16; o > 0; o >>= 1) sm += __shfl_xor_sync(0xffffffffu, sm, o);
  if (lane == 0) nls[warp] = -(mx + logf(sm));   // -lse over j for this s
  __syncthreads();

  if (warp == 0) {
    float v = (lane < 16) ? nls[lane] : -3.4e38f;
    float m2 = v;
#pragma unroll
    for (int o = 16; o > 0; o >>= 1) m2 = fmaxf(m2, __shfl_xor_sync(0xffffffffu, m2, o));
    float s2 = (lane < 16) ? expf(v - m2) : 0.f;
#pragma unroll
    for (int o = 16; o > 0; o >>= 1) s2 += __shfl_xor_sync(0xffffffffu, s2, o);
    if (lane == 0) Msh = m2 + logf(s2) - 2.7725887f;  // lse_s(-lse_j) - log 16
  }
  __syncthreads();

  if (tid < 64) {
    int row = g_order[(half * 4 + b) * 64 + l];
    out[row * 64 + tid] = g_lm[((half * 4 + b) * 64 + l) * 64 + tid] + Msh;
  }
}

// ---------------- launcher ---------------------------------------------------
extern "C" void kernel_launch(void* const* d_in, const int* in_sizes, int n_in,
                              void* d_out, int out_size) {
  const float* params = nullptr;
  const float* heps   = nullptr;
  const int*   labels = nullptr;
  for (int i = 0; i < n_in; i++) {
    if (in_sizes[i] == 1) heps = (const float*)d_in[i];
    else if (in_sizes[i] == 512) labels = (const int*)d_in[i];
    else params = (const float*)d_in[i];
  }
  if (!params) params = (const float*)d_in[0];
  if (!heps)   heps   = (const float*)d_in[1];
  if (!labels) labels = (const int*)d_in[2];

  float* out = (float*)d_out;
  (void)out_size;

  uint32_t s1k0, s1k1, s2k0, s2k1;
  tf2x32_host(0u, 42u, 0u, 0u, &s1k0, &s1k1);
  tf2x32_host(0u, 42u, 0u, 1u, &s2k0, &s2k1);

  setup_kernel<<<64, 256>>>(params, labels, heps);
  main_kernel<<<32768, 128>>>(s1k0, s1k1, s2k0, s2k1, 1u);
  finalize_kernel<<<512, 512>>>(out);
}

// round 15
// speedup vs baseline: 1.0580x; 1.0049x over previous
#include <cuda_runtime.h>
#include <stdint.h>
#include <math.h>

// ============================================================================
// SPEClassifier on GB300. D=256, K=512, L=64, B=8, S=16, C=64.
// R15: main + finalize byte-identical to R14 (main at measured plateau
// ~388.6us). Setup split into 128 blocks (half, l) with warp-shuffle
// reductions: each block gathers its half's 4 support rows (union = all 8)
// and computes one prototype. Target: setup 11.1us -> ~5us.
// ============================================================================

// ---------------- device scratch (no allocation allowed) -------------------
__device__ int   g_order[512];
__device__ float g_qm[8*64*256];
__device__ float g_qv[8*64*256];
__device__ float g_pm[2*64*256];
__device__ float g_pv[2*64*256];
__device__ float g_pC[2*64];
__device__ float g_lm[2*4*64*64];
__device__ float g_tl[2*4*64*16*64];

// ---------------- host threefry (key derivation) ---------------------------
static inline void tf2x32_host(uint32_t k0, uint32_t k1, uint32_t x0, uint32_t x1,
                               uint32_t* o0, uint32_t* o1) {
  uint32_t k2 = k0 ^ k1 ^ 0x1BD11BDAu;
#define ROTL(x,r) (((x)<<(r))|((x)>>(32-(r))))
#define RND(r) { x0 += x1; x1 = ROTL(x1, r); x1 ^= x0; }
  x0 += k0; x1 += k1;
  RND(13) RND(15) RND(26) RND(6)   x0 += k1; x1 += k2 + 1u;
  RND(17) RND(29) RND(16) RND(24)  x0 += k2; x1 += k0 + 2u;
  RND(13) RND(15) RND(26) RND(6)   x0 += k0; x1 += k1 + 3u;
  RND(17) RND(29) RND(16) RND(24)  x0 += k1; x1 += k2 + 4u;
  RND(13) RND(15) RND(26) RND(6)   x0 += k2; x1 += k0 + 5u;
#undef RND
#undef ROTL
  *o0 = x0; *o1 = x1;
}

// r = a*one + b with runtime-opaque one==1 -> IMAD (fma pipe).
__device__ __forceinline__ uint32_t madd1(uint32_t a, uint32_t b, uint32_t one) {
  uint32_t r;
  asm("mad.lo.u32 %0, %1, %2, %3;" : "=r"(r) : "r"(a), "r"(one), "r"(b));
  return r;
}

// threefry2x32 for counter (0, i), x1i = i + k1 pre-added. Returns x0 ^ x1.
__device__ __forceinline__ uint32_t tf_bits(uint32_t x1i, uint32_t k0, uint32_t k1,
                                            uint32_t k2, uint32_t one) {
  uint32_t x0 = madd1(k0, x1i, one);
  uint32_t x1 = __funnelshift_l(x1i, x1i, 13) ^ x0;
#define RND(r) { x0 = madd1(x0, x1, one); x1 = __funnelshift_l(x1, x1, r) ^ x0; }
  RND(15) RND(26) RND(6)
  x0 = madd1(x0, k1, one); x1 = madd1(x1, k2 + 1u, one);
  RND(17) RND(29) RND(16) RND(24)
  x0 = madd1(x0, k2, one); x1 = madd1(x1, k0 + 2u, one);
  RND(13) RND(15) RND(26) RND(6)
  x0 = madd1(x0, k0, one); x1 = madd1(x1, k1 + 3u, one);
  RND(17) RND(29) RND(16) RND(24)
  x0 = madd1(x0, k1, one); x1 = madd1(x1, k2 + 4u, one);
  RND(13) RND(15) RND(26) RND(6)
  x0 = madd1(x0, k2, one); x1 = madd1(x1, k0 + 5u, one);
#undef RND
  return x0 ^ x1;
}

// ---------------- f32x2 packed helpers --------------------------------------
__device__ __forceinline__ uint64_t fma2_(uint64_t a, uint64_t b, uint64_t c) {
  uint64_t d;
  asm("fma.rn.f32x2 %0, %1, %2, %3;" : "=l"(d) : "l"(a), "l"(b), "l"(c));
  return d;
}
__device__ __forceinline__ uint64_t mul2_(uint64_t a, uint64_t b) {
  uint64_t d;
  asm("mul.rn.f32x2 %0, %1, %2;" : "=l"(d) : "l"(a), "l"(b));
  return d;
}
__device__ __forceinline__ uint64_t add2_(uint64_t a, uint64_t b) {
  uint64_t d;
  asm("add.rn.f32x2 %0, %1, %2;" : "=l"(d) : "l"(a), "l"(b));
  return d;
}
__device__ __forceinline__ uint64_t pkuu(uint32_t lo, uint32_t hi) {
  uint64_t d;
  asm("mov.b64 %0, {%1, %2};" : "=l"(d) : "r"(lo), "r"(hi));
  return d;
}
__device__ __forceinline__ uint64_t pkff(float lo, float hi) {
  uint64_t d;
  asm("mov.b64 %0, {%1, %2};" : "=l"(d) : "f"(lo), "f"(hi));
  return d;
}
__device__ __forceinline__ void upff(uint64_t v, float& lo, float& hi) {
  asm("mov.b64 {%0, %1}, %2;" : "=f"(lo), "=f"(hi) : "l"(v));
}
__device__ __forceinline__ uint64_t sp2(float x) {
  uint32_t u = __float_as_uint(x);
  return ((uint64_t)u << 32) | (uint64_t)u;
}

// Rare tail: sqrt2*erfinv for w >= 5 (scalar, immediate coefficients).
__device__ __forceinline__ float tail_e(float w, float u) {
  const float S = 1.41421356237f;
  float sw;
  asm("sqrt.approx.f32 %0, %1;" : "=f"(sw) : "f"(w));
  float v = sw - 3.0f;
  float p = -0.000200214257f * S;
  p = fmaf(p, v, 0.000100950558f * S);
  p = fmaf(p, v, 0.00134934322f * S);
  p = fmaf(p, v, -0.00367342844f * S);
  p = fmaf(p, v, 0.00573950773f * S);
  p = fmaf(p, v, -0.0076224613f * S);
  p = fmaf(p, v, 0.00943887047f * S);
  p = fmaf(p, v, 1.00167406f * S);
  p = fmaf(p, v, 2.83297682f * S);
  return p * u;
}

// Two N(0,1) samples from two random words; returns PACKED (e0,e1). R11 exact.
__device__ __forceinline__ uint64_t pair_normals(uint32_t bits0, uint32_t bits1) {
  const float S = 1.41421356237f;
  uint32_t m0, m1;
  asm("mad.hi.u32 %0, %1, %2, %3;" : "=r"(m0)
      : "r"(bits0), "n"(0x800000), "n"(0x3f800000));
  asm("mad.hi.u32 %0, %1, %2, %3;" : "=r"(m1)
      : "r"(bits1), "n"(0x800000), "n"(0x3f800000));
  uint64_t M = pkuu(m0, m1);
  uint64_t F = add2_(M, sp2(-1.0f));                    // f in [0,1), exact
  uint64_t U = fma2_(F, sp2(2.0f), sp2(-0.99999994f));  // uniform [LO,1)
  uint64_t Zm = fma2_(U, U, sp2(-1.0f));                // u^2-1 = -(1-u^2)
  float zm0, zm1; upff(Zm, zm0, zm1);
  float l0 = __log2f(fabsf(zm0));                       // MUFU.LG2(|zm|)
  float l1 = __log2f(fabsf(zm1));
  uint64_t V = fma2_(pkff(l0, l1), sp2(-0.69314718056f), sp2(-2.5f)); // w-2.5
  uint64_t P = sp2(2.81022636e-08f * S);
  P = fma2_(P, V, sp2(3.43273939e-07f * S));
  P = fma2_(P, V, sp2(-3.5233877e-06f * S));
  P = fma2_(P, V, sp2(-4.39150654e-06f * S));
  P = fma2_(P, V, sp2(0.00021858087f * S));
  P = fma2_(P, V, sp2(-0.00125372503f * S));
  P = fma2_(P, V, sp2(-0.00417768164f * S));
  P = fma2_(P, V, sp2(0.246640727f * S));
  P = fma2_(P, V, sp2(1.50140941f * S));
  uint64_t E = mul2_(P, U);
  // tail: w >= 5 <=> zm >= -e^-5 (~0.34%/sample)
  bool t0 = zm0 > -6.7379470e-3f;
  bool t1 = zm1 > -6.7379470e-3f;
  if (__any_sync(0xffffffffu, t0 || t1)) {
    float e0, e1, u0, u1, v0, v1;
    upff(E, e0, e1);
    upff(U, u0, u1);
    upff(V, v0, v1);
    if (t0) e0 = tail_e(v0 + 2.5f, u0);
    if (t1) e1 = tail_e(v1 + 2.5f, u1);
    E = pkff(e0, e1);
  }
  return E;
}

// ---------------- K1: fused setup, 128 blocks = (half, l) -------------------
// Block (half, l) gathers the 4 support rows for its half (= query rows of
// the other half; union over both blocks covers all 8 rows and all g_order
// entries exactly once) and computes its prototype with shfl reductions.
__global__ __launch_bounds__(256) void setup_kernel(const float* __restrict__ params,
                                                    const int* __restrict__ labels32,
                                                    const float* __restrict__ heps) {
  int bx = blockIdx.x;
  int half = bx >> 6, l = bx & 63;
  int t = threadIdx.x;          // 0..255
  int lane = t & 31, w = t >> 5;

  __shared__ unsigned ball[16];
  __shared__ int rows[8];       // stable order of the 8 rows of class l
  __shared__ int odd_nz;
  __shared__ float sm_m[4][256];
  __shared__ float sm_v[4][256];
  __shared__ float red8[8];

  if (t == 0) odd_nz = 0;
  __syncthreads();
  // dtype detect: any odd int32 word nonzero -> int32 labels
  if (labels32[2 * t + 1] != 0) atomicOr(&odd_nz, 1);
  __syncthreads();
  int stride = odd_nz ? 1 : 2;  // int64 little-endian -> stride 2
  int lab0 = labels32[t * stride];
  int lab1 = labels32[(t + 256) * stride];

  bool f0 = (lab0 == l);
  bool f1 = (lab1 == l);
  unsigned b0 = __ballot_sync(0xffffffffu, f0);
  unsigned b1 = __ballot_sync(0xffffffffu, f1);
  if (lane == 0) { ball[w] = b0; ball[w + 8] = b1; }
  __syncthreads();
  if (f0) {
    int r = __popc(b0 & ((1u << lane) - 1u));
    for (int k = 0; k < w; k++) r += __popc(ball[k]);
    if (r < 8) rows[r] = t;
  }
  if (f1) {
    int r = __popc(b1 & ((1u << lane) - 1u));
    for (int k = 0; k < 8 + w; k++) r += __popc(ball[k]);
    if (r < 8) rows[r] = t + 256;
  }
  __syncthreads();

  // this block owns occurrence indices [sb, sb+4): support rows for `half`
  int sb = half ? 0 : 4;
  if (t < 4) g_order[(sb + t) * 64 + l] = rows[sb + t];

  // gather 4 rows (independent loads; write-through to global for main)
#pragma unroll
  for (int bi = 0; bi < 4; bi++) {
    int row = rows[sb + bi];
    float m = params[row * 512 + t];
    float v = expf(params[row * 512 + 256 + t]);
    sm_m[bi][t] = m; sm_v[bi][t] = v;
    g_qm[((sb + bi) * 64 + l) * 256 + t] = m;
    g_qv[((sb + bi) * 64 + l) * 256 + t] = v;
  }

  // prototype for this half (no cross-block data needed)
  float eps_var = expf(*heps);
  float sinv = 0.f, smi = 0.f;
#pragma unroll
  for (int bi = 0; bi < 4; bi++) {
    float v = eps_var + sm_v[bi][t];
    float inv = 1.0f / v;
    sinv += inv;
    smi = fmaf(sm_m[bi][t], inv, smi);
  }
  float nv = 1.0f / sinv;
  float nm = nv * smi;
  float vp = eps_var + nv;
  float hp = logf(vp);
  g_pm[(half * 64 + l) * 256 + t] = nm;
  g_pv[(half * 64 + l) * 256 + t] = vp;

  // block reduction of (log2pi + hp) via shfl + 8-word shared
  float r = 1.83787707f + hp;
#pragma unroll
  for (int o = 16; o > 0; o >>= 1) r += __shfl_xor_sync(0xffffffffu, r, o);
  if (lane == 0) red8[w] = r;
  __syncthreads();
  if (t == 0) {
    float s = red8[0] + red8[1] + red8[2] + red8[3]
            + red8[4] + red8[5] + red8[6] + red8[7];
    g_pC[half * 64 + l] = -0.5f * s;
  }
}

// ---------------- K2: main Monte-Carlo kernel (byte-identical to R11) -------
__global__ __launch_bounds__(128) void main_kernel(uint32_t s1k0, uint32_t s1k1,
                                                   uint32_t s2k0, uint32_t s2k1,
                                                   uint32_t one) {
  int bx = blockIdx.x;
  int j = bx & 63, l = (bx >> 6) & 63, b = (bx >> 12) & 3, half = bx >> 14;
  uint32_t k0 = half ? s2k0 : s1k0;
  uint32_t k1 = half ? s2k1 : s1k1;
  uint32_t k2 = k0 ^ k1 ^ 0x1BD11BDAu;
  int qb = half * 4 + b;

  __shared__ unsigned long long a2_s[256];   // splat (a, a)
  __shared__ unsigned long long b2_s[256];   // splat (beta, beta)
  __shared__ float red4[4];

  int tid = threadIdx.x;
  int lane = tid & 31, warp = tid >> 5;

  const float* qm = g_qm + (qb * 64 + l) * 256;
  const float* qv = g_qv + (qb * 64 + l) * 256;
  const float* pm = g_pm + (half * 64 + j) * 256;
  const float* pv = g_pv + (half * 64 + j) * 256;

  float lmsum = 0.f;
#pragma unroll
  for (int dd = 0; dd < 2; dd++) {
    int d = tid + dd * 128;
    float m1 = qm[d], v1 = qv[d], m2 = pm[d], v2 = pv[d];
    float vs = v1 + v2;
    float rvs = 1.0f / vs;
    float dm = m1 - m2;
    float a = dm * sqrtf(v2) * rvs;
    float bb = sqrtf(v1 * rvs);
    a2_s[d] = pkff(a, a);
    b2_s[d] = pkff(bb, bb);
    lmsum += 1.8378770664f + logf(vs) + dm * dm * rvs;
  }
  for (int o = 16; o > 0; o >>= 1) lmsum += __shfl_xor_sync(0xffffffffu, lmsum, o);
  if (lane == 0) red4[warp] = lmsum;
  __syncthreads();
  if (tid == 0) {
    float s = red4[0] + red4[1] + red4[2] + red4[3];
    g_lm[((half * 4 + b) * 64 + l) * 64 + j] = -0.5f * s;
  }

  float Cj = g_pC[half * 64 + j];

  uint32_t i00 = ((((uint32_t)(b * 64 + l)) * 16u + (uint32_t)warp) * 64u +
                  (uint32_t)j) * 256u + (uint32_t)lane;
  uint32_t k1p0 = k1 + i00;
  uint32_t k1p1 = k1p0 + 65536u;
  uint32_t k1p2 = k1p0 + 131072u;
  uint32_t k1p3 = k1p0 + 196608u;

  uint64_t ACC01 = 0, ACC23 = 0;       // packed (acc_s, acc_{s+4}) pairs

#pragma unroll 2
  for (int u = 0; u < 8; u++) {
    uint64_t A2 = a2_s[lane + 32 * u];
    uint64_t B2 = b2_s[lane + 32 * u];
    uint32_t du = 32u * (uint32_t)u;

    // pair A: s = warp, warp+4
    {
      uint32_t c0 = tf_bits(madd1(du, k1p0, one), k0, k1, k2, one);
      uint32_t c1 = tf_bits(madd1(du, k1p1, one), k0, k1, k2, one);
      uint64_t E = pair_normals(c0, c1);
      uint64_t T = fma2_(B2, E, A2);
      ACC01 = fma2_(T, T, ACC01);
    }
    // pair B: s = warp+8, warp+12
    {
      uint32_t c2 = tf_bits(madd1(du, k1p2, one), k0, k1, k2, one);
      uint32_t c3 = tf_bits(madd1(du, k1p3, one), k0, k1, k2, one);
      uint64_t E = pair_normals(c2, c3);
      uint64_t T = fma2_(B2, E, A2);
      ACC23 = fma2_(T, T, ACC23);
    }
  }

  float acc0, acc1, acc2, acc3;
  upff(ACC01, acc0, acc1);
  upff(ACC23, acc2, acc3);

#pragma unroll
  for (int o = 16; o > 0; o >>= 1) {
    acc0 += __shfl_xor_sync(0xffffffffu, acc0, o);
    acc1 += __shfl_xor_sync(0xffffffffu, acc1, o);
    acc2 += __shfl_xor_sync(0xffffffffu, acc2, o);
    acc3 += __shfl_xor_sync(0xffffffffu, acc3, o);
  }
  if (lane == 0) {
    int base = (((half * 4 + b) * 64 + l) * 16 + warp) * 64 + j;
    g_tl[base]           = Cj - 0.5f * acc0;
    g_tl[base + 4 * 64]  = Cj - 0.5f * acc1;
    g_tl[base + 8 * 64]  = Cj - 0.5f * acc2;
    g_tl[base + 12 * 64] = Cj - 0.5f * acc3;
  }
}

// ---------------- K3: logsumexps + scatter (warp per s) ---------------------
__global__ __launch_bounds__(512) void finalize_kernel(float* __restrict__ out) {
  int bx = blockIdx.x;
  int l = bx & 63, b = (bx >> 6) & 3, half = bx >> 8;
  int tid = threadIdx.x;
  int lane = tid & 31, warp = tid >> 5;   // warp = s (0..15)

  __shared__ float nls[16];
  __shared__ float Msh;

  int base = (((half * 4 + b) * 64 + l) * 16 + warp) * 64;
  float v0 = g_tl[base + lane];
  float v1 = g_tl[base + 32 + lane];
  float mx = fmaxf(v0, v1);
#pragma unroll
  for (int o = 16; o > 0; o >>= 1) mx = fmaxf(mx, __shfl_xor_sync(0xffffffffu, mx, o));
  float sm = expf(v0 - mx) + expf(v1 - mx);
#pragma unroll
  for (int o = 16; o > 0; o >>= 1) sm += __shfl_xor_sync(0xffffffffu, sm, o);
  if (lane == 0) nls[warp] = -(mx + logf(sm));   // -lse over j for this s
  __syncthreads();

  if (warp == 0) {
    float v = (lane < 16) ? nls[lane] : -3.4e38f;
    float m2 = v;
#pragma unroll
    for (int o = 16; o > 0; o >>= 1) m2 = fmaxf(m2, __shfl_xor_sync(0xffffffffu, m2, o));
    float s2 = (lane < 16) ? expf(v - m2) : 0.f;
#pragma unroll
    for (int o = 16; o > 0; o >>= 1) s2 += __shfl_xor_sync(0xffffffffu, s2, o);
    if (lane == 0) Msh = m2 + logf(s2) - 2.7725887f;  // lse_s(-lse_j) - log 16
  }
  __syncthreads();

  if (tid < 64) {
    int row = g_order[(half * 4 + b) * 64 + l];
    out[row * 64 + tid] = g_lm[((half * 4 + b) * 64 + l) * 64 + tid] + Msh;
  }
}

// ---------------- launcher ---------------------------------------------------
extern "C" void kernel_launch(void* const* d_in, const int* in_sizes, int n_in,
                              void* d_out, int out_size) {
  const float* params = nullptr;
  const float* heps   = nullptr;
  const int*   labels = nullptr;
  for (int i = 0; i < n_in; i++) {
    if (in_sizes[i] == 1) heps = (const float*)d_in[i];
    else if (in_sizes[i] == 512) labels = (const int*)d_in[i];
    else params = (const float*)d_in[i];
  }
  if (!params) params = (const float*)d_in[0];
  if (!heps)   heps   = (const float*)d_in[1];
  if (!labels) labels = (const int*)d_in[2];

  float* out = (float*)d_out;
  (void)out_size;

  uint32_t s1k0, s1k1, s2k0, s2k1;
  tf2x32_host(0u, 42u, 0u, 0u, &s1k0, &s1k1);
  tf2x32_host(0u, 42u, 0u, 1u, &s2k0, &s2k1);

  setup_kernel<<<128, 256>>>(params, labels, heps);
  main_kernel<<<32768, 128>>>(s1k0, s1k1, s2k0, s2k1, 1u);
  finalize_kernel<<<512, 512>>>(out);
}

// round 16
// speedup vs baseline: 1.0626x; 1.0043x over previous
#include <cuda_runtime.h>
#include <stdint.h>
#include <math.h>

// ============================================================================
// SPEClassifier on GB300. D=256, K=512, L=64, B=8, S=16, C=64.
// R16: main computation byte-identical to R11/R15 plateau; finalize FUSED
// into main's epilogue via threadfence-reduction (last block of each 64-block
// (half,b,l) group does the double-LSE + scatter; counter self-resets for
// graph-replay determinism). 3 launches -> 2.
// ============================================================================

// ---------------- device scratch (no allocation allowed) -------------------
__device__ int   g_order[512];
__device__ float g_qm[8*64*256];
__device__ float g_qv[8*64*256];
__device__ float g_pm[2*64*256];
__device__ float g_pv[2*64*256];
__device__ float g_pC[2*64];
__device__ float g_lm[2*4*64*64];
__device__ float g_tl[2*4*64*16*64];
__device__ int   g_cnt[512];           // zero-init; self-resetting

// ---------------- host threefry (key derivation) ---------------------------
static inline void tf2x32_host(uint32_t k0, uint32_t k1, uint32_t x0, uint32_t x1,
                               uint32_t* o0, uint32_t* o1) {
  uint32_t k2 = k0 ^ k1 ^ 0x1BD11BDAu;
#define ROTL(x,r) (((x)<<(r))|((x)>>(32-(r))))
#define RND(r) { x0 += x1; x1 = ROTL(x1, r); x1 ^= x0; }
  x0 += k0; x1 += k1;
  RND(13) RND(15) RND(26) RND(6)   x0 += k1; x1 += k2 + 1u;
  RND(17) RND(29) RND(16) RND(24)  x0 += k2; x1 += k0 + 2u;
  RND(13) RND(15) RND(26) RND(6)   x0 += k0; x1 += k1 + 3u;
  RND(17) RND(29) RND(16) RND(24)  x0 += k1; x1 += k2 + 4u;
  RND(13) RND(15) RND(26) RND(6)   x0 += k2; x1 += k0 + 5u;
#undef RND
#undef ROTL
  *o0 = x0; *o1 = x1;
}

// r = a*one + b with runtime-opaque one==1 -> IMAD (fma pipe).
__device__ __forceinline__ uint32_t madd1(uint32_t a, uint32_t b, uint32_t one) {
  uint32_t r;
  asm("mad.lo.u32 %0, %1, %2, %3;" : "=r"(r) : "r"(a), "r"(one), "r"(b));
  return r;
}

// threefry2x32 for counter (0, i), x1i = i + k1 pre-added. Returns x0 ^ x1.
__device__ __forceinline__ uint32_t tf_bits(uint32_t x1i, uint32_t k0, uint32_t k1,
                                            uint32_t k2, uint32_t one) {
  uint32_t x0 = madd1(k0, x1i, one);
  uint32_t x1 = __funnelshift_l(x1i, x1i, 13) ^ x0;
#define RND(r) { x0 = madd1(x0, x1, one); x1 = __funnelshift_l(x1, x1, r) ^ x0; }
  RND(15) RND(26) RND(6)
  x0 = madd1(x0, k1, one); x1 = madd1(x1, k2 + 1u, one);
  RND(17) RND(29) RND(16) RND(24)
  x0 = madd1(x0, k2, one); x1 = madd1(x1, k0 + 2u, one);
  RND(13) RND(15) RND(26) RND(6)
  x0 = madd1(x0, k0, one); x1 = madd1(x1, k1 + 3u, one);
  RND(17) RND(29) RND(16) RND(24)
  x0 = madd1(x0, k1, one); x1 = madd1(x1, k2 + 4u, one);
  RND(13) RND(15) RND(26) RND(6)
  x0 = madd1(x0, k2, one); x1 = madd1(x1, k0 + 5u, one);
#undef RND
  return x0 ^ x1;
}

// ---------------- f32x2 packed helpers --------------------------------------
__device__ __forceinline__ uint64_t fma2_(uint64_t a, uint64_t b, uint64_t c) {
  uint64_t d;
  asm("fma.rn.f32x2 %0, %1, %2, %3;" : "=l"(d) : "l"(a), "l"(b), "l"(c));
  return d;
}
__device__ __forceinline__ uint64_t mul2_(uint64_t a, uint64_t b) {
  uint64_t d;
  asm("mul.rn.f32x2 %0, %1, %2;" : "=l"(d) : "l"(a), "l"(b));
  return d;
}
__device__ __forceinline__ uint64_t add2_(uint64_t a, uint64_t b) {
  uint64_t d;
  asm("add.rn.f32x2 %0, %1, %2;" : "=l"(d) : "l"(a), "l"(b));
  return d;
}
__device__ __forceinline__ uint64_t pkuu(uint32_t lo, uint32_t hi) {
  uint64_t d;
  asm("mov.b64 %0, {%1, %2};" : "=l"(d) : "r"(lo), "r"(hi));
  return d;
}
__device__ __forceinline__ uint64_t pkff(float lo, float hi) {
  uint64_t d;
  asm("mov.b64 %0, {%1, %2};" : "=l"(d) : "f"(lo), "f"(hi));
  return d;
}
__device__ __forceinline__ void upff(uint64_t v, float& lo, float& hi) {
  asm("mov.b64 {%0, %1}, %2;" : "=f"(lo), "=f"(hi) : "l"(v));
}
__device__ __forceinline__ uint64_t sp2(float x) {
  uint32_t u = __float_as_uint(x);
  return ((uint64_t)u << 32) | (uint64_t)u;
}

// Rare tail: sqrt2*erfinv for w >= 5 (scalar, immediate coefficients).
__device__ __forceinline__ float tail_e(float w, float u) {
  const float S = 1.41421356237f;
  float sw;
  asm("sqrt.approx.f32 %0, %1;" : "=f"(sw) : "f"(w));
  float v = sw - 3.0f;
  float p = -0.000200214257f * S;
  p = fmaf(p, v, 0.000100950558f * S);
  p = fmaf(p, v, 0.00134934322f * S);
  p = fmaf(p, v, -0.00367342844f * S);
  p = fmaf(p, v, 0.00573950773f * S);
  p = fmaf(p, v, -0.0076224613f * S);
  p = fmaf(p, v, 0.00943887047f * S);
  p = fmaf(p, v, 1.00167406f * S);
  p = fmaf(p, v, 2.83297682f * S);
  return p * u;
}

// Two N(0,1) samples from two random words; returns PACKED (e0,e1). R11 exact.
__device__ __forceinline__ uint64_t pair_normals(uint32_t bits0, uint32_t bits1) {
  const float S = 1.41421356237f;
  uint32_t m0, m1;
  asm("mad.hi.u32 %0, %1, %2, %3;" : "=r"(m0)
      : "r"(bits0), "n"(0x800000), "n"(0x3f800000));
  asm("mad.hi.u32 %0, %1, %2, %3;" : "=r"(m1)
      : "r"(bits1), "n"(0x800000), "n"(0x3f800000));
  uint64_t M = pkuu(m0, m1);
  uint64_t F = add2_(M, sp2(-1.0f));                    // f in [0,1), exact
  uint64_t U = fma2_(F, sp2(2.0f), sp2(-0.99999994f));  // uniform [LO,1)
  uint64_t Zm = fma2_(U, U, sp2(-1.0f));                // u^2-1 = -(1-u^2)
  float zm0, zm1; upff(Zm, zm0, zm1);
  float l0 = __log2f(fabsf(zm0));                       // MUFU.LG2(|zm|)
  float l1 = __log2f(fabsf(zm1));
  uint64_t V = fma2_(pkff(l0, l1), sp2(-0.69314718056f), sp2(-2.5f)); // w-2.5
  uint64_t P = sp2(2.81022636e-08f * S);
  P = fma2_(P, V, sp2(3.43273939e-07f * S));
  P = fma2_(P, V, sp2(-3.5233877e-06f * S));
  P = fma2_(P, V, sp2(-4.39150654e-06f * S));
  P = fma2_(P, V, sp2(0.00021858087f * S));
  P = fma2_(P, V, sp2(-0.00125372503f * S));
  P = fma2_(P, V, sp2(-0.00417768164f * S));
  P = fma2_(P, V, sp2(0.246640727f * S));
  P = fma2_(P, V, sp2(1.50140941f * S));
  uint64_t E = mul2_(P, U);
  // tail: w >= 5 <=> zm >= -e^-5 (~0.34%/sample)
  bool t0 = zm0 > -6.7379470e-3f;
  bool t1 = zm1 > -6.7379470e-3f;
  if (__any_sync(0xffffffffu, t0 || t1)) {
    float e0, e1, u0, u1, v0, v1;
    upff(E, e0, e1);
    upff(U, u0, u1);
    upff(V, v0, v1);
    if (t0) e0 = tail_e(v0 + 2.5f, u0);
    if (t1) e1 = tail_e(v1 + 2.5f, u1);
    E = pkff(e0, e1);
  }
  return E;
}

// ---------------- K1: fused setup, 128 blocks = (half, l) -------------------
__global__ __launch_bounds__(256) void setup_kernel(const float* __restrict__ params,
                                                    const int* __restrict__ labels32,
                                                    const float* __restrict__ heps) {
  int bx = blockIdx.x;
  int half = bx >> 6, l = bx & 63;
  int t = threadIdx.x;          // 0..255
  int lane = t & 31, w = t >> 5;

  __shared__ unsigned ball[16];
  __shared__ int rows[8];
  __shared__ int odd_nz;
  __shared__ float sm_m[4][256];
  __shared__ float sm_v[4][256];
  __shared__ float red8[8];

  if (t == 0) odd_nz = 0;
  __syncthreads();
  if (labels32[2 * t + 1] != 0) atomicOr(&odd_nz, 1);
  __syncthreads();
  int stride = odd_nz ? 1 : 2;  // int64 little-endian -> stride 2
  int lab0 = labels32[t * stride];
  int lab1 = labels32[(t + 256) * stride];

  bool f0 = (lab0 == l);
  bool f1 = (lab1 == l);
  unsigned b0 = __ballot_sync(0xffffffffu, f0);
  unsigned b1 = __ballot_sync(0xffffffffu, f1);
  if (lane == 0) { ball[w] = b0; ball[w + 8] = b1; }
  __syncthreads();
  if (f0) {
    int r = __popc(b0 & ((1u << lane) - 1u));
    for (int k = 0; k < w; k++) r += __popc(ball[k]);
    if (r < 8) rows[r] = t;
  }
  if (f1) {
    int r = __popc(b1 & ((1u << lane) - 1u));
    for (int k = 0; k < 8 + w; k++) r += __popc(ball[k]);
    if (r < 8) rows[r] = t + 256;
  }
  __syncthreads();

  int sb = half ? 0 : 4;
  if (t < 4) g_order[(sb + t) * 64 + l] = rows[sb + t];

#pragma unroll
  for (int bi = 0; bi < 4; bi++) {
    int row = rows[sb + bi];
    float m = params[row * 512 + t];
    float v = expf(params[row * 512 + 256 + t]);
    sm_m[bi][t] = m; sm_v[bi][t] = v;
    g_qm[((sb + bi) * 64 + l) * 256 + t] = m;
    g_qv[((sb + bi) * 64 + l) * 256 + t] = v;
  }

  float eps_var = expf(*heps);
  float sinv = 0.f, smi = 0.f;
#pragma unroll
  for (int bi = 0; bi < 4; bi++) {
    float v = eps_var + sm_v[bi][t];
    float inv = 1.0f / v;
    sinv += inv;
    smi = fmaf(sm_m[bi][t], inv, smi);
  }
  float nv = 1.0f / sinv;
  float nm = nv * smi;
  float vp = eps_var + nv;
  float hp = logf(vp);
  g_pm[(half * 64 + l) * 256 + t] = nm;
  g_pv[(half * 64 + l) * 256 + t] = vp;

  float r = 1.83787707f + hp;
#pragma unroll
  for (int o = 16; o > 0; o >>= 1) r += __shfl_xor_sync(0xffffffffu, r, o);
  if (lane == 0) red8[w] = r;
  __syncthreads();
  if (t == 0) {
    float s = red8[0] + red8[1] + red8[2] + red8[3]
            + red8[4] + red8[5] + red8[6] + red8[7];
    g_pC[half * 64 + l] = -0.5f * s;
  }
}

// ---------------- K2: main MC kernel + fused group finalize -----------------
__global__ __launch_bounds__(128) void main_kernel(uint32_t s1k0, uint32_t s1k1,
                                                   uint32_t s2k0, uint32_t s2k1,
                                                   uint32_t one,
                                                   float* __restrict__ out) {
  int bx = blockIdx.x;
  int j = bx & 63, l = (bx >> 6) & 63, b = (bx >> 12) & 3, half = bx >> 14;
  uint32_t k0 = half ? s2k0 : s1k0;
  uint32_t k1 = half ? s2k1 : s1k1;
  uint32_t k2 = k0 ^ k1 ^ 0x1BD11BDAu;
  int qb = half * 4 + b;
  int gid = (half * 4 + b) * 64 + l;      // finalize group id (0..511)

  __shared__ unsigned long long a2_s[256];   // splat (a, a)
  __shared__ unsigned long long b2_s[256];   // splat (beta, beta)
  __shared__ float red4[4];
  __shared__ int slast;
  __shared__ float nls[16];
  __shared__ float Msh;

  int tid = threadIdx.x;
  int lane = tid & 31, warp = tid >> 5;

  const float* qm = g_qm + (qb * 64 + l) * 256;
  const float* qv = g_qv + (qb * 64 + l) * 256;
  const float* pm = g_pm + (half * 64 + j) * 256;
  const float* pv = g_pv + (half * 64 + j) * 256;

  float lmsum = 0.f;
#pragma unroll
  for (int dd = 0; dd < 2; dd++) {
    int d = tid + dd * 128;
    float m1 = qm[d], v1 = qv[d], m2 = pm[d], v2 = pv[d];
    float vs = v1 + v2;
    float rvs = 1.0f / vs;
    float dm = m1 - m2;
    float a = dm * sqrtf(v2) * rvs;
    float bb = sqrtf(v1 * rvs);
    a2_s[d] = pkff(a, a);
    b2_s[d] = pkff(bb, bb);
    lmsum += 1.8378770664f + logf(vs) + dm * dm * rvs;
  }
  for (int o = 16; o > 0; o >>= 1) lmsum += __shfl_xor_sync(0xffffffffu, lmsum, o);
  if (lane == 0) red4[warp] = lmsum;
  __syncthreads();
  if (tid == 0) {
    float s = red4[0] + red4[1] + red4[2] + red4[3];
    g_lm[gid * 64 + j] = -0.5f * s;
  }

  float Cj = g_pC[half * 64 + j];

  uint32_t i00 = ((((uint32_t)(b * 64 + l)) * 16u + (uint32_t)warp) * 64u +
                  (uint32_t)j) * 256u + (uint32_t)lane;
  uint32_t k1p0 = k1 + i00;
  uint32_t k1p1 = k1p0 + 65536u;
  uint32_t k1p2 = k1p0 + 131072u;
  uint32_t k1p3 = k1p0 + 196608u;

  uint64_t ACC01 = 0, ACC23 = 0;       // packed (acc_s, acc_{s+4}) pairs

#pragma unroll 2
  for (int u = 0; u < 8; u++) {
    uint64_t A2 = a2_s[lane + 32 * u];
    uint64_t B2 = b2_s[lane + 32 * u];
    uint32_t du = 32u * (uint32_t)u;

    // pair A: s = warp, warp+4
    {
      uint32_t c0 = tf_bits(madd1(du, k1p0, one), k0, k1, k2, one);
      uint32_t c1 = tf_bits(madd1(du, k1p1, one), k0, k1, k2, one);
      uint64_t E = pair_normals(c0, c1);
      uint64_t T = fma2_(B2, E, A2);
      ACC01 = fma2_(T, T, ACC01);
    }
    // pair B: s = warp+8, warp+12
    {
      uint32_t c2 = tf_bits(madd1(du, k1p2, one), k0, k1, k2, one);
      uint32_t c3 = tf_bits(madd1(du, k1p3, one), k0, k1, k2, one);
      uint64_t E = pair_normals(c2, c3);
      uint64_t T = fma2_(B2, E, A2);
      ACC23 = fma2_(T, T, ACC23);
    }
  }

  float acc0, acc1, acc2, acc3;
  upff(ACC01, acc0, acc1);
  upff(ACC23, acc2, acc3);

#pragma unroll
  for (int o = 16; o > 0; o >>= 1) {
    acc0 += __shfl_xor_sync(0xffffffffu, acc0, o);
    acc1 += __shfl_xor_sync(0xffffffffu, acc1, o);
    acc2 += __shfl_xor_sync(0xffffffffu, acc2, o);
    acc3 += __shfl_xor_sync(0xffffffffu, acc3, o);
  }
  if (lane == 0) {
    int base = (gid * 16 + warp) * 64 + j;
    g_tl[base]           = Cj - 0.5f * acc0;
    g_tl[base + 4 * 64]  = Cj - 0.5f * acc1;
    g_tl[base + 8 * 64]  = Cj - 0.5f * acc2;
    g_tl[base + 12 * 64] = Cj - 0.5f * acc3;
  }

  // -------- fused finalize: last block of the 64-block group does the LSE --
  __threadfence();
  if (tid == 0) {
    int old = atomicAdd(&g_cnt[gid], 1);
    slast = (old == 63) ? 1 : 0;
  }
  __syncthreads();
  if (!slast) return;

  // 4 warps x 4 s-values each: lse over j (64 values) per s
#pragma unroll
  for (int k = 0; k < 4; k++) {
    int s = k * 4 + warp;
    int base2 = (gid * 16 + s) * 64;
    float v0 = g_tl[base2 + lane];
    float v1 = g_tl[base2 + 32 + lane];
    float mx = fmaxf(v0, v1);
#pragma unroll
    for (int o = 16; o > 0; o >>= 1) mx = fmaxf(mx, __shfl_xor_sync(0xffffffffu, mx, o));
    float sm = expf(v0 - mx) + expf(v1 - mx);
#pragma unroll
    for (int o = 16; o > 0; o >>= 1) sm += __shfl_xor_sync(0xffffffffu, sm, o);
    if (lane == 0) nls[s] = -(mx + logf(sm));
  }
  __syncthreads();
  if (warp == 0) {
    float v = (lane < 16) ? nls[lane] : -3.4e38f;
    float m2 = v;
#pragma unroll
    for (int o = 16; o > 0; o >>= 1) m2 = fmaxf(m2, __shfl_xor_sync(0xffffffffu, m2, o));
    float s2 = (lane < 16) ? expf(v - m2) : 0.f;
#pragma unroll
    for (int o = 16; o > 0; o >>= 1) s2 += __shfl_xor_sync(0xffffffffu, s2, o);
    if (lane == 0) Msh = m2 + logf(s2) - 2.7725887f;  // lse_s(-lse_j) - log 16
  }
  __syncthreads();

  int row = g_order[gid];
  if (tid < 64) out[row * 64 + tid] = g_lm[gid * 64 + tid] + Msh;
  if (tid == 64) g_cnt[gid] = 0;        // self-reset for graph replays
}

// ---------------- launcher ---------------------------------------------------
extern "C" void kernel_launch(void* const* d_in, const int* in_sizes, int n_in,
                              void* d_out, int out_size) {
  const float* params = nullptr;
  const float* heps   = nullptr;
  const int*   labels = nullptr;
  for (int i = 0; i < n_in; i++) {
    if (in_sizes[i] == 1) heps = (const float*)d_in[i];
    else if (in_sizes[i] == 512) labels = (const int*)d_in[i];
    else params = (const float*)d_in[i];
  }
  if (!params) params = (const float*)d_in[0];
  if (!heps)   heps   = (const float*)d_in[1];
  if (!labels) labels = (const int*)d_in[2];

  float* out = (float*)d_out;
  (void)out_size;

  uint32_t s1k0, s1k1, s2k0, s2k1;
  tf2x32_host(0u, 42u, 0u, 0u, &s1k0, &s1k1);
  tf2x32_host(0u, 42u, 0u, 1u, &s2k0, &s2k1);

  setup_kernel<<<128, 256>>>(params, labels, heps);
  main_kernel<<<32768, 128>>>(s1k0, s1k1, s2k0, s2k1, 1u, out);
}